// round 6
// baseline (speedup 1.0000x reference)
#include <cuda_runtime.h>
#include <cuda_fp16.h>
#include <stdint.h>

// ======================= constants =======================
static constexpr int NLAYERS = 8;
static constexpr int HID = 128;
static constexpr int BATCH = 262144;
static constexpr int NT = 256;             // 8 warps
static constexpr int MTILE = 256;          // 8 warps x M=32 per warp
static constexpr int NBLK = BATCH / MTILE; // 1024

// padded weight image: row = 136 halves (272B) -> conflict-free ldmatrix
static constexpr int WROW = 136;
static constexpr int WIMG_HALVES = HID * WROW;      // 17408
static constexpr int WIMG_BYTES = WIMG_HALVES * 2;  // 34816
__device__ __align__(16) __half g_wh[NLAYERS * WIMG_HALVES];

// smem layout
static constexpr uint32_t XROW = 132;                     // floats per x row (pad)
static constexpr uint32_t OF_X = 0;
static constexpr uint32_t X_BYTES = MTILE * XROW * 4;     // 135168
static constexpr uint32_t OF_W0 = X_BYTES;                // 135168
static constexpr uint32_t OF_W1 = OF_W0 + WIMG_BYTES;     // 169984
static constexpr uint32_t OF_B0 = OF_W1 + WIMG_BYTES;     // 204800
static constexpr uint32_t OF_B1 = OF_B0 + 512;            // 205312
static constexpr uint32_t SMEM_BYTES = OF_B1 + 512;       // 205824

// ======================= PTX helpers (baseline compute_103-safe) =======================
__device__ __forceinline__ uint32_t smem_to_u32(const void* p) {
    uint32_t a;
    asm("{ .reg .u64 t; cvta.to.shared.u64 t, %1; cvt.u32.u64 %0, t; }" : "=r"(a) : "l"(p));
    return a;
}

#define CP_ASYNC16(dst, src) \
    asm volatile("cp.async.cg.shared.global [%0], [%1], 16;" :: "r"(dst), "l"(src))
#define CP_COMMIT() asm volatile("cp.async.commit_group;")
#define CP_WAIT0()  asm volatile("cp.async.wait_group 0;")

#define LDSM_X4(r0, r1, r2, r3, addr) \
    asm volatile("ldmatrix.sync.aligned.m8n8.x4.shared.b16 {%0,%1,%2,%3}, [%4];" \
                 : "=r"(r0), "=r"(r1), "=r"(r2), "=r"(r3) : "r"(addr))

#define MMA16816(d, a, b0_, b1_) \
    asm volatile("mma.sync.aligned.m16n8k16.row.col.f32.f16.f16.f32 " \
                 "{%0,%1,%2,%3}, {%4,%5,%6,%7}, {%8,%9}, {%0,%1,%2,%3};" \
                 : "+f"((d)[0]), "+f"((d)[1]), "+f"((d)[2]), "+f"((d)[3]) \
                 : "r"((a)[0]), "r"((a)[1]), "r"((a)[2]), "r"((a)[3]), \
                   "r"(b0_), "r"(b1_))

// pack fp32 pair -> fp16x2
__device__ __forceinline__ uint32_t pack2(float v0, float v1) {
    __half2 h = __floats2half2_rn(v0, v1);
    return *reinterpret_cast<uint32_t*>(&h);
}

// ======================= prep: fp32 weights -> padded fp16 image =======================
__global__ void ElasticMLP_prep(const float* __restrict__ w) {
    int i = blockIdx.x * blockDim.x + threadIdx.x;
    if (i >= NLAYERS * WIMG_HALVES) return;
    int l = i / WIMG_HALVES;
    int rem = i - l * WIMG_HALVES;
    int n = rem / WROW;
    int k = rem - n * WROW;
    float v = (k < HID) ? w[(l * HID + n) * HID + k] : 0.0f;
    g_wh[i] = __float2half_rn(v);
}

// ======================= main fused MLP =======================
__global__ void __launch_bounds__(NT, 1)
ElasticMLP_main(const float* __restrict__ x, const float* __restrict__ b,
                float* __restrict__ out) {
    extern __shared__ __align__(16) char sm[];
    const uint32_t smu = smem_to_u32(sm);
    float* xs = reinterpret_cast<float*>(sm + OF_X);

    const int tid = threadIdx.x;
    const int lane = tid & 31;
    const int wid = tid >> 5;
    const int rw = wid * 16;          // warp's row base for M-set 0 (M-set 1 at +128)
    const int qr = lane >> 2;         // 0..7
    const int qc = (lane & 3) * 2;    // 0,2,4,6

    // ---- stage x tile (256 rows), layer-0 weights, layer-0 bias ----
    const float* xg = x + (size_t)blockIdx.x * (MTILE * HID);
    {
        const char* wsrc = reinterpret_cast<const char*>(g_wh);
        for (int i = tid; i < MTILE * (HID / 4); i += NT) {   // 8192 16B chunks
            int r = i >> 5, ch = i & 31;
            CP_ASYNC16(smu + OF_X + (uint32_t)(r * (XROW * 4) + ch * 16),
                       xg + r * HID + ch * 4);
        }
        for (int i = tid; i < WIMG_BYTES / 16; i += NT)
            CP_ASYNC16(smu + OF_W0 + (uint32_t)(i * 16), wsrc + i * 16);
        if (tid < 32) CP_ASYNC16(smu + OF_B0 + (uint32_t)(tid * 16), b + tid * 4);
    }
    CP_COMMIT();
    CP_WAIT0();
    __syncthreads();

    // ---- build layer-0 A fragments from x (fp16), two M-sets ----
    uint32_t A[2][8][4];
    #pragma unroll
    for (int ms = 0; ms < 2; ms++) {
        const int rbase = ms * 128 + rw + qr;
        #pragma unroll
        for (int kt = 0; kt < 8; kt++) {
            const float* p0 = xs + rbase * XROW + kt * 16 + qc;
            float2 v00 = *reinterpret_cast<const float2*>(p0);
            float2 v01 = *reinterpret_cast<const float2*>(p0 + 8);
            float2 v10 = *reinterpret_cast<const float2*>(p0 + 8 * XROW);
            float2 v11 = *reinterpret_cast<const float2*>(p0 + 8 * XROW + 8);
            A[ms][kt][0] = pack2(v00.x, v00.y);
            A[ms][kt][1] = pack2(v10.x, v10.y);
            A[ms][kt][2] = pack2(v01.x, v01.y);
            A[ms][kt][3] = pack2(v11.x, v11.y);
        }
    }

    // ldmatrix.x4 per-lane address offset
    const int g = lane >> 3, rsub = lane & 7;
    const uint32_t lds_off =
        (uint32_t)(((((g >= 2) ? 8 : 0) + rsub) * WROW + (g & 1) * 8) * 2);

    #pragma unroll 1
    for (int l = 0; l < NLAYERS; l++) {
        // prefetch next layer's weights/bias into the other buffer
        if (l + 1 < NLAYERS) {
            const char* wsrc = reinterpret_cast<const char*>(g_wh + (size_t)(l + 1) * WIMG_HALVES);
            const uint32_t dstW = smu + (((l + 1) & 1) ? OF_W1 : OF_W0);
            for (int i = tid; i < WIMG_BYTES / 16; i += NT)
                CP_ASYNC16(dstW + (uint32_t)(i * 16), wsrc + i * 16);
            if (tid < 32)
                CP_ASYNC16(smu + (((l + 1) & 1) ? OF_B1 : OF_B0) + (uint32_t)(tid * 16),
                           b + (l + 1) * HID + tid * 4);
            CP_COMMIT();
        }

        const uint32_t smW = smu + ((l & 1) ? OF_W1 : OF_W0);
        const uint32_t wbase = smW + lds_off;
        const float* bs = reinterpret_cast<const float*>(sm + ((l & 1) ? OF_B1 : OF_B0));

        float D[2][16][4];
        #pragma unroll
        for (int ms = 0; ms < 2; ms++)
            #pragma unroll
            for (int i = 0; i < 16; i++) {
                D[ms][i][0] = 0.f; D[ms][i][1] = 0.f;
                D[ms][i][2] = 0.f; D[ms][i][3] = 0.f;
            }

        // ---- MMA: software-pipelined ldmatrix (B double-buffer) ----
        // addr(kt, p) = wbase + p*(16*WROW*2) + kt*32
        uint32_t Bb[2][4];
        LDSM_X4(Bb[0][0], Bb[0][1], Bb[0][2], Bb[0][3], wbase);
        #pragma unroll
        for (int kt = 0; kt < 8; kt++) {
            #pragma unroll
            for (int p = 0; p < 8; p++) {
                const int cur = (kt * 8 + p) & 1;
                const int nxt = cur ^ 1;
                // prefetch next group (wraps to (0,0) on last iter; harmless)
                const int np = (p + 1) & 7;
                const int nkt = (p == 7) ? ((kt + 1) & 7) : kt;
                LDSM_X4(Bb[nxt][0], Bb[nxt][1], Bb[nxt][2], Bb[nxt][3],
                        wbase + (uint32_t)(np * (16 * WROW * 2) + nkt * 32));
                MMA16816(D[0][2 * p],     A[0][kt], Bb[cur][0], Bb[cur][1]);
                MMA16816(D[0][2 * p + 1], A[0][kt], Bb[cur][2], Bb[cur][3]);
                MMA16816(D[1][2 * p],     A[1][kt], Bb[cur][0], Bb[cur][1]);
                MMA16816(D[1][2 * p + 1], A[1][kt], Bb[cur][2], Bb[cur][3]);
            }
        }

        // ---- epilogue ----
        if (l < NLAYERS - 1) {
            const bool skip = (l > 0);
            #pragma unroll
            for (int ms = 0; ms < 2; ms++) {
                const int rbase = ms * 128 + rw + qr;
                #pragma unroll
                for (int nt = 0; nt < 16; nt++) {
                    const int c0 = nt * 8 + qc;
                    float2 bb = *reinterpret_cast<const float2*>(bs + c0);
                    float v0 = fmaxf(D[ms][nt][0] + bb.x, 0.f);
                    float v1 = fmaxf(D[ms][nt][1] + bb.y, 0.f);
                    float v2 = fmaxf(D[ms][nt][2] + bb.x, 0.f);
                    float v3 = fmaxf(D[ms][nt][3] + bb.y, 0.f);
                    if (skip) {
                        const float* px = xs + rbase * XROW + c0;
                        float2 x0 = *reinterpret_cast<const float2*>(px);
                        float2 x1 = *reinterpret_cast<const float2*>(px + 8 * XROW);
                        v0 += x0.x; v1 += x0.y; v2 += x1.x; v3 += x1.y;
                    }
                    // repack D -> next layer A frags (identical (row, col-pair) mapping)
                    const int kt = nt >> 1, h2 = (nt & 1) * 2;
                    A[ms][kt][h2]     = pack2(v0, v1);
                    A[ms][kt][h2 + 1] = pack2(v2, v3);
                }
            }
            CP_WAIT0();
            __syncthreads();
        } else {
            #pragma unroll
            for (int ms = 0; ms < 2; ms++) {
                const int rbase = ms * 128 + rw + qr;
                float* og = out + ((size_t)blockIdx.x * MTILE + rbase) * HID;
                #pragma unroll
                for (int nt = 0; nt < 16; nt++) {
                    const int c0 = nt * 8 + qc;
                    float2 bb = *reinterpret_cast<const float2*>(bs + c0);
                    const float* px = xs + rbase * XROW + c0;
                    float2 x0 = *reinterpret_cast<const float2*>(px);
                    float2 x1 = *reinterpret_cast<const float2*>(px + 8 * XROW);
                    float2 o0, o1;
                    o0.x = fmaxf(D[ms][nt][0] + bb.x, 0.f) + x0.x;
                    o0.y = fmaxf(D[ms][nt][1] + bb.y, 0.f) + x0.y;
                    o1.x = fmaxf(D[ms][nt][2] + bb.x, 0.f) + x1.x;
                    o1.y = fmaxf(D[ms][nt][3] + bb.y, 0.f) + x1.y;
                    *reinterpret_cast<float2*>(og + c0) = o0;
                    *reinterpret_cast<float2*>(og + 8 * HID + c0) = o1;
                }
            }
        }
    }
}

// ======================= launch =======================
extern "C" void kernel_launch(void* const* d_in, const int* in_sizes, int n_in,
                              void* d_out, int out_size) {
    const float* x = (const float*)d_in[0];
    const float* w = (const float*)d_in[1];
    const float* b = (const float*)d_in[2];
    float* out = (float*)d_out;

    ElasticMLP_prep<<<(NLAYERS * WIMG_HALVES + 255) / 256, 256>>>(w);

    cudaFuncSetAttribute(ElasticMLP_main,
                         cudaFuncAttributeMaxDynamicSharedMemorySize, SMEM_BYTES);
    ElasticMLP_main<<<NBLK, NT, SMEM_BYTES>>>(x, b, out);
}

// round 7
// speedup vs baseline: 1.0885x; 1.0885x over previous
#include <cuda_runtime.h>
#include <cuda_fp16.h>
#include <stdint.h>

// ======================= constants =======================
static constexpr int NLAYERS = 8;
static constexpr int HID = 128;
static constexpr int BATCH = 262144;
static constexpr int NT = 256;             // 8 warps
static constexpr int MTILE = 256;          // 8 warps x M=32 per warp (2 M-sets of 16)
static constexpr int NBLK = BATCH / MTILE; // 1024

// padded weight image: row = 136 halves (272B) -> conflict-free ldmatrix
static constexpr int WROW = 136;
static constexpr int WIMG_HALVES = HID * WROW;      // 17408
static constexpr int WIMG_BYTES = WIMG_HALVES * 2;  // 34816
__device__ __align__(16) __half g_wh[NLAYERS * WIMG_HALVES];

// smem layout
static constexpr uint32_t XROW = 132;                     // floats per x row (pad)
static constexpr uint32_t OF_X = 0;
static constexpr uint32_t X_BYTES = MTILE * XROW * 4;     // 135168
static constexpr uint32_t OF_W0 = X_BYTES;                // 135168
static constexpr uint32_t OF_W1 = OF_W0 + WIMG_BYTES;     // 169984
static constexpr uint32_t OF_B0 = OF_W1 + WIMG_BYTES;     // 204800
static constexpr uint32_t OF_B1 = OF_B0 + 512;            // 205312
static constexpr uint32_t SMEM_BYTES = OF_B1 + 512;       // 205824

// ======================= PTX helpers (baseline compute_103-safe) =======================
__device__ __forceinline__ uint32_t smem_to_u32(const void* p) {
    uint32_t a;
    asm("{ .reg .u64 t; cvta.to.shared.u64 t, %1; cvt.u32.u64 %0, t; }" : "=r"(a) : "l"(p));
    return a;
}

#define CP_ASYNC16(dst, src) \
    asm volatile("cp.async.cg.shared.global [%0], [%1], 16;" :: "r"(dst), "l"(src))
#define CP_COMMIT() asm volatile("cp.async.commit_group;")
#define CP_WAIT0()  asm volatile("cp.async.wait_group 0;")

#define LDSM_X4(r0, r1, r2, r3, addr) \
    asm volatile("ldmatrix.sync.aligned.m8n8.x4.shared.b16 {%0,%1,%2,%3}, [%4];" \
                 : "=r"(r0), "=r"(r1), "=r"(r2), "=r"(r3) : "r"(addr))

#define MMA16816(d, a, b0_, b1_) \
    asm volatile("mma.sync.aligned.m16n8k16.row.col.f32.f16.f16.f32 " \
                 "{%0,%1,%2,%3}, {%4,%5,%6,%7}, {%8,%9}, {%0,%1,%2,%3};" \
                 : "+f"((d)[0]), "+f"((d)[1]), "+f"((d)[2]), "+f"((d)[3]) \
                 : "r"((a)[0]), "r"((a)[1]), "r"((a)[2]), "r"((a)[3]), \
                   "r"(b0_), "r"(b1_))

// pack fp32 pair -> fp16x2
__device__ __forceinline__ uint32_t pack2(float v0, float v1) {
    __half2 h = __floats2half2_rn(v0, v1);
    return *reinterpret_cast<uint32_t*>(&h);
}

// ======================= prep: fp32 weights -> padded fp16 image =======================
__global__ void ElasticMLP_prep(const float* __restrict__ w) {
    int i = blockIdx.x * blockDim.x + threadIdx.x;
    if (i >= NLAYERS * WIMG_HALVES) return;
    int l = i / WIMG_HALVES;
    int rem = i - l * WIMG_HALVES;
    int n = rem / WROW;
    int k = rem - n * WROW;
    float v = (k < HID) ? w[(l * HID + n) * HID + k] : 0.0f;
    g_wh[i] = __float2half_rn(v);
}

// ======================= main fused MLP =======================
__global__ void __launch_bounds__(NT, 1)
ElasticMLP_main(const float* __restrict__ x, const float* __restrict__ b,
                float* __restrict__ out) {
    extern __shared__ __align__(16) char sm[];
    const uint32_t smu = smem_to_u32(sm);
    float* xs = reinterpret_cast<float*>(sm + OF_X);

    const int tid = threadIdx.x;
    const int lane = tid & 31;
    const int wid = tid >> 5;
    const int rw = wid * 16;          // warp's row base for M-set 0 (M-set 1 at +128)
    const int qr = lane >> 2;         // 0..7
    const int qc = (lane & 3) * 2;    // 0,2,4,6

    // ---- stage x tile (256 rows), layer-0 weights, layer-0 bias ----
    const float* xg = x + (size_t)blockIdx.x * (MTILE * HID);
    {
        const char* wsrc = reinterpret_cast<const char*>(g_wh);
        for (int i = tid; i < MTILE * (HID / 4); i += NT) {   // 8192 16B chunks
            int r = i >> 5, ch = i & 31;
            CP_ASYNC16(smu + OF_X + (uint32_t)(r * (XROW * 4) + ch * 16),
                       xg + r * HID + ch * 4);
        }
        for (int i = tid; i < WIMG_BYTES / 16; i += NT)
            CP_ASYNC16(smu + OF_W0 + (uint32_t)(i * 16), wsrc + i * 16);
        if (tid < 32) CP_ASYNC16(smu + OF_B0 + (uint32_t)(tid * 16), b + tid * 4);
    }
    CP_COMMIT();
    CP_WAIT0();
    __syncthreads();

    // ---- build layer-0 A fragments from x (fp16), two M-sets ----
    uint32_t A[2][8][4];
    #pragma unroll
    for (int ms = 0; ms < 2; ms++) {
        const int rbase = ms * 128 + rw + qr;
        #pragma unroll
        for (int kt = 0; kt < 8; kt++) {
            const float* p0 = xs + rbase * XROW + kt * 16 + qc;
            float2 v00 = *reinterpret_cast<const float2*>(p0);
            float2 v01 = *reinterpret_cast<const float2*>(p0 + 8);
            float2 v10 = *reinterpret_cast<const float2*>(p0 + 8 * XROW);
            float2 v11 = *reinterpret_cast<const float2*>(p0 + 8 * XROW + 8);
            A[ms][kt][0] = pack2(v00.x, v00.y);
            A[ms][kt][1] = pack2(v10.x, v10.y);
            A[ms][kt][2] = pack2(v01.x, v01.y);
            A[ms][kt][3] = pack2(v11.x, v11.y);
        }
    }

    // ldmatrix.x4 per-lane address offset
    const int g = lane >> 3, rsub = lane & 7;
    const uint32_t lds_off =
        (uint32_t)(((((g >= 2) ? 8 : 0) + rsub) * WROW + (g & 1) * 8) * 2);

    #pragma unroll 1
    for (int l = 0; l < NLAYERS; l++) {
        // prefetch next layer's weights/bias into the other buffer
        if (l + 1 < NLAYERS) {
            const char* wsrc = reinterpret_cast<const char*>(g_wh + (size_t)(l + 1) * WIMG_HALVES);
            const uint32_t dstW = smu + (((l + 1) & 1) ? OF_W1 : OF_W0);
            for (int i = tid; i < WIMG_BYTES / 16; i += NT)
                CP_ASYNC16(dstW + (uint32_t)(i * 16), wsrc + i * 16);
            if (tid < 32)
                CP_ASYNC16(smu + (((l + 1) & 1) ? OF_B1 : OF_B0) + (uint32_t)(tid * 16),
                           b + (l + 1) * HID + tid * 4);
            CP_COMMIT();
        }

        const uint32_t wbase = smu + ((l & 1) ? OF_W1 : OF_W0) + lds_off;
        const float* bs = reinterpret_cast<const float*>(sm + ((l & 1) ? OF_B1 : OF_B0));
        const bool last = (l == NLAYERS - 1);
        const bool skip = (l > 0);

        uint32_t An[2][8][4];   // next-layer A fragments, filled per p-group

        // ---- n-outer / k-inner: per 16-col group p, accumulate then epilogue ----
        #pragma unroll
        for (int p = 0; p < 8; p++) {
            float Dp[2][2][4];  // [ms][npair][quad] — only this group's accumulators
            #pragma unroll
            for (int ms = 0; ms < 2; ms++)
                #pragma unroll
                for (int np = 0; np < 2; np++) {
                    Dp[ms][np][0] = 0.f; Dp[ms][np][1] = 0.f;
                    Dp[ms][np][2] = 0.f; Dp[ms][np][3] = 0.f;
                }

            const uint32_t pb = wbase + (uint32_t)(p * (16 * WROW * 2));
            #pragma unroll
            for (int kt = 0; kt < 8; kt++) {
                uint32_t b0, b1, b2, b3;
                LDSM_X4(b0, b1, b2, b3, pb + (uint32_t)(kt * 32));
                MMA16816(Dp[0][0], A[0][kt], b0, b1);
                MMA16816(Dp[0][1], A[0][kt], b2, b3);
                MMA16816(Dp[1][0], A[1][kt], b0, b1);
                MMA16816(Dp[1][1], A[1][kt], b2, b3);
            }

            // ---- immediate epilogue for cols [16p, 16p+16) ----
            #pragma unroll
            for (int ms = 0; ms < 2; ms++) {
                const int rbase = ms * 128 + rw + qr;
                if (!last) {
                    #pragma unroll
                    for (int np = 0; np < 2; np++) {
                        const int c0 = p * 16 + np * 8 + qc;
                        float2 bb = *reinterpret_cast<const float2*>(bs + c0);
                        float v0 = fmaxf(Dp[ms][np][0] + bb.x, 0.f);
                        float v1 = fmaxf(Dp[ms][np][1] + bb.y, 0.f);
                        float v2 = fmaxf(Dp[ms][np][2] + bb.x, 0.f);
                        float v3 = fmaxf(Dp[ms][np][3] + bb.y, 0.f);
                        if (skip) {
                            const float* px = xs + rbase * XROW + c0;
                            float2 x0 = *reinterpret_cast<const float2*>(px);
                            float2 x1 = *reinterpret_cast<const float2*>(px + 8 * XROW);
                            v0 += x0.x; v1 += x0.y; v2 += x1.x; v3 += x1.y;
                        }
                        An[ms][p][2 * np]     = pack2(v0, v1);
                        An[ms][p][2 * np + 1] = pack2(v2, v3);
                    }
                } else {
                    float* og = out + ((size_t)blockIdx.x * MTILE + rbase) * HID;
                    #pragma unroll
                    for (int np = 0; np < 2; np++) {
                        const int c0 = p * 16 + np * 8 + qc;
                        float2 bb = *reinterpret_cast<const float2*>(bs + c0);
                        const float* px = xs + rbase * XROW + c0;
                        float2 x0 = *reinterpret_cast<const float2*>(px);
                        float2 x1 = *reinterpret_cast<const float2*>(px + 8 * XROW);
                        float2 o0, o1;
                        o0.x = fmaxf(Dp[ms][np][0] + bb.x, 0.f) + x0.x;
                        o0.y = fmaxf(Dp[ms][np][1] + bb.y, 0.f) + x0.y;
                        o1.x = fmaxf(Dp[ms][np][2] + bb.x, 0.f) + x1.x;
                        o1.y = fmaxf(Dp[ms][np][3] + bb.y, 0.f) + x1.y;
                        *reinterpret_cast<float2*>(og + c0) = o0;
                        *reinterpret_cast<float2*>(og + 8 * HID + c0) = o1;
                    }
                }
            }
        }

        // ---- rotate activations, sync for next weight buffer ----
        if (!last) {
            #pragma unroll
            for (int ms = 0; ms < 2; ms++)
                #pragma unroll
                for (int kt = 0; kt < 8; kt++) {
                    A[ms][kt][0] = An[ms][kt][0];
                    A[ms][kt][1] = An[ms][kt][1];
                    A[ms][kt][2] = An[ms][kt][2];
                    A[ms][kt][3] = An[ms][kt][3];
                }
            CP_WAIT0();
            __syncthreads();
        }
    }
}

// ======================= launch =======================
extern "C" void kernel_launch(void* const* d_in, const int* in_sizes, int n_in,
                              void* d_out, int out_size) {
    const float* x = (const float*)d_in[0];
    const float* w = (const float*)d_in[1];
    const float* b = (const float*)d_in[2];
    float* out = (float*)d_out;

    ElasticMLP_prep<<<(NLAYERS * WIMG_HALVES + 255) / 256, 256>>>(w);

    cudaFuncSetAttribute(ElasticMLP_main,
                         cudaFuncAttributeMaxDynamicSharedMemorySize, SMEM_BYTES);
    ElasticMLP_main<<<NBLK, NT, SMEM_BYTES>>>(x, b, out);
}

// round 9
// speedup vs baseline: 1.1105x; 1.0203x over previous
#include <cuda_runtime.h>
#include <cuda_fp16.h>
#include <stdint.h>

// ======================= constants =======================
static constexpr int NLAYERS = 8;
static constexpr int HID = 128;
static constexpr int BATCH = 262144;
static constexpr int NT = 256;             // 8 warps
static constexpr int MTILE = 256;          // 8 warps x M=32 per warp (2 M-sets of 16)
static constexpr int NBLK = BATCH / MTILE; // 1024

// padded weight image: row = 136 halves (272B) -> conflict-free ldmatrix
static constexpr int WROW = 136;
static constexpr int WIMG_HALVES = HID * WROW;      // 17408
static constexpr int WIMG_BYTES = WIMG_HALVES * 2;  // 34816
__device__ __align__(16) __half g_wh[NLAYERS * WIMG_HALVES];

// smem layout (x stored as fp16, row stride 136 halves = 272 B)
static constexpr uint32_t XROWH = 136;                    // halves per x row
static constexpr uint32_t XROWB = XROWH * 2;              // 272 bytes
static constexpr uint32_t OF_X = 0;
static constexpr uint32_t X_BYTES = MTILE * XROWB;        // 69632
static constexpr uint32_t OF_W0 = X_BYTES;                // 69632
static constexpr uint32_t OF_W1 = OF_W0 + WIMG_BYTES;     // 104448
static constexpr uint32_t OF_B0 = OF_W1 + WIMG_BYTES;     // 139264
static constexpr uint32_t OF_B1 = OF_B0 + 512;            // 139776
static constexpr uint32_t SMEM_BYTES = OF_B1 + 512;       // 140288

// ======================= PTX helpers (baseline compute_103-safe) =======================
__device__ __forceinline__ uint32_t smem_to_u32(const void* p) {
    uint32_t a;
    asm("{ .reg .u64 t; cvta.to.shared.u64 t, %1; cvt.u32.u64 %0, t; }" : "=r"(a) : "l"(p));
    return a;
}

#define CP_ASYNC16(dst, src) \
    asm volatile("cp.async.cg.shared.global [%0], [%1], 16;" :: "r"(dst), "l"(src))
#define CP_COMMIT() asm volatile("cp.async.commit_group;")
#define CP_WAIT0()  asm volatile("cp.async.wait_group 0;")

#define LDSM_X4(r0, r1, r2, r3, addr) \
    asm volatile("ldmatrix.sync.aligned.m8n8.x4.shared.b16 {%0,%1,%2,%3}, [%4];" \
                 : "=r"(r0), "=r"(r1), "=r"(r2), "=r"(r3) : "r"(addr))

#define MMA16816(d, a, b0_, b1_) \
    asm volatile("mma.sync.aligned.m16n8k16.row.col.f32.f16.f16.f32 " \
                 "{%0,%1,%2,%3}, {%4,%5,%6,%7}, {%8,%9}, {%0,%1,%2,%3};" \
                 : "+f"((d)[0]), "+f"((d)[1]), "+f"((d)[2]), "+f"((d)[3]) \
                 : "r"((a)[0]), "r"((a)[1]), "r"((a)[2]), "r"((a)[3]), \
                   "r"(b0_), "r"(b1_))

#define LDS32(r, addr) \
    asm volatile("ld.shared.b32 %0, [%1];" : "=r"(r) : "r"(addr))

// pack fp32 pair -> fp16x2
__device__ __forceinline__ uint32_t pack2(float v0, float v1) {
    __half2 h = __floats2half2_rn(v0, v1);
    return *reinterpret_cast<uint32_t*>(&h);
}
__device__ __forceinline__ uint32_t hadd2u(uint32_t a, uint32_t b) {
    __half2 r = __hadd2(*reinterpret_cast<__half2*>(&a), *reinterpret_cast<__half2*>(&b));
    return *reinterpret_cast<uint32_t*>(&r);
}

// ======================= prep: fp32 weights -> padded fp16 image =======================
__global__ void ElasticMLP_prep(const float* __restrict__ w) {
    int i = blockIdx.x * blockDim.x + threadIdx.x;
    if (i >= NLAYERS * WIMG_HALVES) return;
    int l = i / WIMG_HALVES;
    int rem = i - l * WIMG_HALVES;
    int n = rem / WROW;
    int k = rem - n * WROW;
    float v = (k < HID) ? w[(l * HID + n) * HID + k] : 0.0f;
    g_wh[i] = __float2half_rn(v);
}

// ======================= main fused MLP =======================
__global__ void __launch_bounds__(NT, 1)
ElasticMLP_main(const float* __restrict__ x, const float* __restrict__ b,
                float* __restrict__ out) {
    extern __shared__ __align__(16) char sm[];
    const uint32_t smu = smem_to_u32(sm);

    const int tid = threadIdx.x;
    const int lane = tid & 31;
    const int wid = tid >> 5;
    const int rw = wid * 16;          // warp's row base for M-set 0 (M-set 1 at +128)
    const int qr = lane >> 2;         // 0..7
    const int qc = (lane & 3) * 2;    // 0,2,4,6

    // ---- stage layer-0 weights + bias (cp.async), x tile converted to fp16 ----
    {
        const char* wsrc = reinterpret_cast<const char*>(g_wh);
        for (int i = tid; i < WIMG_BYTES / 16; i += NT)
            CP_ASYNC16(smu + OF_W0 + (uint32_t)(i * 16), wsrc + i * 16);
        if (tid < 32) CP_ASYNC16(smu + OF_B0 + (uint32_t)(tid * 16), b + tid * 4);
        CP_COMMIT();

        const float4* xg = reinterpret_cast<const float4*>(x + (size_t)blockIdx.x * (MTILE * HID));
        for (int i = tid; i < MTILE * (HID / 4); i += NT) {   // 8192 float4 chunks
            int r = i >> 5, ch = i & 31;
            float4 v = xg[i];
            uint2 pk = make_uint2(pack2(v.x, v.y), pack2(v.z, v.w));
            *reinterpret_cast<uint2*>(sm + OF_X + r * XROWB + ch * 8) = pk;
        }
        CP_WAIT0();
    }
    __syncthreads();

    // ---- build layer-0 A fragments: direct packed loads from fp16 x ----
    uint32_t A[2][8][4];
    #pragma unroll
    for (int ms = 0; ms < 2; ms++) {
        const int rbase = ms * 128 + rw + qr;
        #pragma unroll
        for (int kt = 0; kt < 8; kt++) {
            const uint32_t a0 = smu + OF_X + (uint32_t)(rbase * XROWB + (kt * 16 + qc) * 2);
            LDS32(A[ms][kt][0], a0);
            LDS32(A[ms][kt][1], a0 + 8 * XROWB);
            LDS32(A[ms][kt][2], a0 + 16);
            LDS32(A[ms][kt][3], a0 + 8 * XROWB + 16);
        }
    }

    // ldmatrix.x4 per-lane address offset
    const int g = lane >> 3, rsub = lane & 7;
    const uint32_t lds_off =
        (uint32_t)(((((g >= 2) ? 8 : 0) + rsub) * WROW + (g & 1) * 8) * 2);

    #pragma unroll 1
    for (int l = 0; l < NLAYERS; l++) {
        // prefetch next layer's weights/bias into the other buffer
        if (l + 1 < NLAYERS) {
            const char* wsrc = reinterpret_cast<const char*>(g_wh + (size_t)(l + 1) * WIMG_HALVES);
            const uint32_t dstW = smu + (((l + 1) & 1) ? OF_W1 : OF_W0);
            for (int i = tid; i < WIMG_BYTES / 16; i += NT)
                CP_ASYNC16(dstW + (uint32_t)(i * 16), wsrc + i * 16);
            if (tid < 32)
                CP_ASYNC16(smu + (((l + 1) & 1) ? OF_B1 : OF_B0) + (uint32_t)(tid * 16),
                           b + (l + 1) * HID + tid * 4);
            CP_COMMIT();
        }

        const uint32_t wbase = smu + ((l & 1) ? OF_W1 : OF_W0) + lds_off;
        const float* bs = reinterpret_cast<const float*>(sm + ((l & 1) ? OF_B1 : OF_B0));
        const bool last = (l == NLAYERS - 1);
        const bool skip = (l > 0);

        uint32_t An[2][8][4];   // next-layer A fragments, filled per p-group

        // ---- n-outer / k-inner: per 16-col group p, accumulate then epilogue ----
        #pragma unroll
        for (int p = 0; p < 8; p++) {
            float Dp[2][2][4];  // [ms][npair][quad]
            #pragma unroll
            for (int ms = 0; ms < 2; ms++)
                #pragma unroll
                for (int np = 0; np < 2; np++) {
                    Dp[ms][np][0] = 0.f; Dp[ms][np][1] = 0.f;
                    Dp[ms][np][2] = 0.f; Dp[ms][np][3] = 0.f;
                }

            const uint32_t pb = wbase + (uint32_t)(p * (16 * WROW * 2));
            #pragma unroll
            for (int kt = 0; kt < 8; kt++) {
                uint32_t b0, b1, b2, b3;
                LDSM_X4(b0, b1, b2, b3, pb + (uint32_t)(kt * 32));
                MMA16816(Dp[0][0], A[0][kt], b0, b1);
                MMA16816(Dp[0][1], A[0][kt], b2, b3);
                MMA16816(Dp[1][0], A[1][kt], b0, b1);
                MMA16816(Dp[1][1], A[1][kt], b2, b3);
            }

            // ---- immediate epilogue for cols [16p, 16p+16) ----
            #pragma unroll
            for (int ms = 0; ms < 2; ms++) {
                const int rbase = ms * 128 + rw + qr;
                if (!last) {
                    #pragma unroll
                    for (int np = 0; np < 2; np++) {
                        const int c0 = p * 16 + np * 8 + qc;
                        float2 bb = *reinterpret_cast<const float2*>(bs + c0);
                        float v0 = fmaxf(Dp[ms][np][0] + bb.x, 0.f);
                        float v1 = fmaxf(Dp[ms][np][1] + bb.y, 0.f);
                        float v2 = fmaxf(Dp[ms][np][2] + bb.x, 0.f);
                        float v3 = fmaxf(Dp[ms][np][3] + bb.y, 0.f);
                        uint32_t h01 = pack2(v0, v1);
                        uint32_t h23 = pack2(v2, v3);
                        if (skip) {
                            const uint32_t xa = smu + OF_X + (uint32_t)(rbase * XROWB + c0 * 2);
                            uint32_t x0, x1;
                            LDS32(x0, xa);
                            LDS32(x1, xa + 8 * XROWB);
                            h01 = hadd2u(h01, x0);
                            h23 = hadd2u(h23, x1);
                        }
                        An[ms][p][2 * np]     = h01;
                        An[ms][p][2 * np + 1] = h23;
                    }
                } else {
                    float* og = out + ((size_t)blockIdx.x * MTILE + rbase) * HID;
                    #pragma unroll
                    for (int np = 0; np < 2; np++) {
                        const int c0 = p * 16 + np * 8 + qc;
                        float2 bb = *reinterpret_cast<const float2*>(bs + c0);
                        const uint32_t xa = smu + OF_X + (uint32_t)(rbase * XROWB + c0 * 2);
                        uint32_t xu0, xu1;
                        LDS32(xu0, xa);
                        LDS32(xu1, xa + 8 * XROWB);
                        float2 x0 = __half22float2(*reinterpret_cast<__half2*>(&xu0));
                        float2 x1 = __half22float2(*reinterpret_cast<__half2*>(&xu1));
                        float2 o0, o1;
                        o0.x = fmaxf(Dp[ms][np][0] + bb.x, 0.f) + x0.x;
                        o0.y = fmaxf(Dp[ms][np][1] + bb.y, 0.f) + x0.y;
                        o1.x = fmaxf(Dp[ms][np][2] + bb.x, 0.f) + x1.x;
                        o1.y = fmaxf(Dp[ms][np][3] + bb.y, 0.f) + x1.y;
                        *reinterpret_cast<float2*>(og + c0) = o0;
                        *reinterpret_cast<float2*>(og + 8 * HID + c0) = o1;
                    }
                }
            }
        }

        // ---- rotate activations, sync for next weight buffer ----
        if (!last) {
            #pragma unroll
            for (int ms = 0; ms < 2; ms++)
                #pragma unroll
                for (int kt = 0; kt < 8; kt++) {
                    A[ms][kt][0] = An[ms][kt][0];
                    A[ms][kt][1] = An[ms][kt][1];
                    A[ms][kt][2] = An[ms][kt][2];
                    A[ms][kt][3] = An[ms][kt][3];
                }
            CP_WAIT0();
            __syncthreads();
        }
    }
}

// ======================= launch =======================
extern "C" void kernel_launch(void* const* d_in, const int* in_sizes, int n_in,
                              void* d_out, int out_size) {
    const float* x = (const float*)d_in[0];
    const float* w = (const float*)d_in[1];
    const float* b = (const float*)d_in[2];
    float* out = (float*)d_out;

    ElasticMLP_prep<<<(NLAYERS * WIMG_HALVES + 255) / 256, 256>>>(w);

    cudaFuncSetAttribute(ElasticMLP_main,
                         cudaFuncAttributeMaxDynamicSharedMemorySize, SMEM_BYTES);
    ElasticMLP_main<<<NBLK, NT, SMEM_BYTES>>>(x, b, out);
}